// round 14
// baseline (speedup 1.0000x reference)
#include <cuda_runtime.h>
#include <cuda_bf16.h>
#include <math.h>

#define Bb 8
#define Nn 8192
#define Ss 2048
#define Kk 32
#define EPSc 1e-5f
#define ALPHAc 0.2f

typedef unsigned long long u64;

// ---- packed f32x2 helpers (Blackwell) ----
#define PACKX2(out, lo, hi) \
    asm("mov.b64 %0, {%1, %2};" : "=l"(out) : "f"(lo), "f"(hi))
#define UNPACKX2(lo, hi, in) \
    asm("mov.b64 {%0, %1}, %2;" : "=f"(lo), "=f"(hi) : "l"(in))
#define ADDX2(d, a, b) \
    asm("add.rn.f32x2 %0, %1, %2;" : "=l"(d) : "l"(a), "l"(b))
#define MULX2(d, a, b) \
    asm("mul.rn.f32x2 %0, %1, %2;" : "=l"(d) : "l"(a), "l"(b))
#define FMAX2(d, a, b, c) \
    asm("fma.rn.f32x2 %0, %1, %2, %3;" : "=l"(d) : "l"(a), "l"(b), "l"(c))

// ---- release/acquire for producer-consumer handoff ----
__device__ __forceinline__ void st_rel(int* p, int v) {
    asm volatile("st.release.gpu.global.s32 [%0], %1;" :: "l"(p), "r"(v) : "memory");
}
__device__ __forceinline__ int ld_acq(const int* p) {
    int v;
    asm volatile("ld.acquire.gpu.global.s32 %0, [%1];" : "=r"(v) : "l"(p) : "memory");
    return v;
}

// ---------------- scratch (device globals; no allocations) ----------------
__device__ int   g_fps_idx[Bb * Ss];                        // -1 = not yet produced
__device__ int   g_ctr;                                     // work-item counter
__device__ __align__(16) float g_F[(size_t)Bb * Nn * 64];   // [xyz(3)|points(61)]
__device__ __align__(16) float g_W0p[32 * 136];
__device__ __align__(16) float g_W1p[32 * 136];
__device__ __align__(16) float g_W2p[64 * 136];
__device__ __align__(16) float g_Ap[3 * 8704];
__device__ float g_b0[64], g_b1[64], g_b2[128];

// ============================================================================
// prep kernel (launch 1): buildF + fold weights + interleave a + init flags/ctr
// ============================================================================
__global__ void __launch_bounds__(256) prep_kernel(
    const float* __restrict__ xyz, const float* __restrict__ pts,
    const float* w0, const float* b0, const float* g0, const float* be0, const float* m0, const float* v0,
    const float* w1, const float* b1, const float* g1, const float* be1, const float* m1, const float* v1,
    const float* w2, const float* b2, const float* g2, const float* be2, const float* m2, const float* v2,
    const float* __restrict__ a) {
    __shared__ float tile[64][65];
    int blk = blockIdx.x;
    int tid = threadIdx.x;
    if (blk < 1024) {
        int b = blk >> 7;
        int n0 = (blk & 127) * 64;
        int nl = tid & 63;
        int cl = tid >> 6;
        for (int c = cl; c < 64; c += 4) {
            int n = n0 + nl;
            float v = (c < 3) ? xyz[((size_t)b * 3 + c) * Nn + n]
                              : pts[((size_t)b * 61 + (c - 3)) * Nn + n];
            tile[c][nl] = v;
        }
        __syncthreads();
        int c = tid & 63;
        int nb = tid >> 6;
        for (int nn = nb; nn < 64; nn += 4)
            g_F[((size_t)(b * Nn + n0 + nn)) * 64 + c] = tile[c][nn];
    } else if (blk < 1088) {
        int t = (blk - 1024) * 256 + tid;
        if (t < 4096) {
            int o = t >> 6, c = t & 63;
            float sc = g0[o] / sqrtf(v0[o] + EPSc);
            g_W0p[(o >> 1) * 136 + c * 2 + (o & 1)] = w0[t] * sc;
            if (c == 0) g_b0[o] = (b0[o] - m0[o]) * sc + be0[o];
        } else if (t < 8192) {
            int i = t - 4096;
            int o = i >> 6, c = i & 63;
            float sc = g1[o] / sqrtf(v1[o] + EPSc);
            g_W1p[(o >> 1) * 136 + c * 2 + (o & 1)] = w1[i] * sc;
            if (c == 0) g_b1[o] = (b1[o] - m1[o]) * sc + be1[o];
        } else if (t < 16384) {
            int i = t - 8192;
            int o = i >> 6, c = i & 63;
            float sc = g2[o] / sqrtf(v2[o] + EPSc);
            g_W2p[(o >> 1) * 136 + c * 2 + (o & 1)] = w2[i] * sc;
            if (c == 0) g_b2[o] = (b2[o] - m2[o]) * sc + be2[o];
        }
    } else if (blk < 1154) {
        int e = (blk - 1088) * 256 + tid;
        if (e < 131 * 128) {
            int c = e >> 7, d = e & 127;
            int tt = c >> 6, cc = c & 63;
            g_Ap[tt * 8704 + (d >> 1) * 136 + cc * 2 + (d & 1)] = a[(size_t)c * 128 + d];
        }
    } else {
        int i = (blk - 1154) * 256 + tid;
        if (i < Bb * Ss) g_fps_idx[i] = -1;
        if (blk == 1154 && tid == 0) g_ctr = 0;
    }
}

// ============================================================================
// Mega kernel (launch 2): 296 blocks x 256 threads, 108,160 B dynamic smem,
// 2 CTAs/SM — consumers have EXACTLY the R7 fused residency/shape.
//   blocks 0..7 : FPS producers (one per batch), 32 pts/thread, xyz in smem
//                 arrays; st.release each produced index.
//   blocks 8+   : persistent consumers; loop on atomicAdd(g_ctr) items.
//                 item i -> b = i&7, s0 = (i>>3)*2 (matches production order);
//                 spin ld.acquire until both centroids exist, then ball query
//                 + verbatim R7 fused pipeline on 2 groups.
// ============================================================================
#define GSTR 68
#define GROWS 2244          // 33*68
#define GFSTR 132
#define GFROWS 4356         // 33*132
#define CATROWS 4224        // 32*132
#define SMFLOATS 27040      // 108,160 B (producer uses first 24,576 floats)

template <int COUT, int OSTR, int OROWS>
__device__ __forceinline__ void mlp_layer(const float* __restrict__ Wgp,
                                          const float* __restrict__ bg,
                                          float* Wsh, float* bsh,
                                          const float* in, float* out, int tid) {
    constexpr int NPAIR = COUT / 2;
    __syncthreads();
    {
        const float4* src = (const float4*)Wgp;
        float4* dst = (float4*)Wsh;
        for (int idx = tid; idx < NPAIR * 34; idx += 256) dst[idx] = src[idx];
    }
    if (tid < COUT) bsh[tid] = bg[tid];
    __syncthreads();

    constexpr int T = COUT / 32;                 // output-pairs per thread
    int team = tid >> 7, l = tid & 127, po = l & 7, og = l >> 3;
    const float* inb = in + team * GROWS;
    float* outb = out + team * OROWS;

    u64 acc2[4 * T];
#pragma unroll
    for (int i = 0; i < 4 * T; i++) acc2[i] = 0ull;

#pragma unroll 2
    for (int cc = 0; cc < 16; cc++) {
        u64 ivd[4][4];
#pragma unroll
        for (int pp = 0; pp < 4; pp++) {
            float4 iv = *(const float4*)(inb + (po + 8 * pp) * GSTR + cc * 4);
            PACKX2(ivd[pp][0], iv.x, iv.x);
            PACKX2(ivd[pp][1], iv.y, iv.y);
            PACKX2(ivd[pp][2], iv.z, iv.z);
            PACKX2(ivd[pp][3], iv.w, iv.w);
        }
#pragma unroll
        for (int t = 0; t < T; t++) {
            int q = og + 16 * t;
            ulonglong2 w01 = *(const ulonglong2*)(Wsh + q * 136 + cc * 8);
            ulonglong2 w23 = *(const ulonglong2*)(Wsh + q * 136 + cc * 8 + 4);
#pragma unroll
            for (int pp = 0; pp < 4; pp++) {
                FMAX2(acc2[pp * T + t], ivd[pp][0], w01.x, acc2[pp * T + t]);
                FMAX2(acc2[pp * T + t], ivd[pp][1], w01.y, acc2[pp * T + t]);
                FMAX2(acc2[pp * T + t], ivd[pp][2], w23.x, acc2[pp * T + t]);
                FMAX2(acc2[pp * T + t], ivd[pp][3], w23.y, acc2[pp * T + t]);
            }
        }
    }
#pragma unroll
    for (int t = 0; t < T; t++) {
        int q = og + 16 * t;
        float blo = bsh[2 * q], bhi = bsh[2 * q + 1];
#pragma unroll
        for (int pp = 0; pp < 4; pp++) {
            float lo, hi;
            UNPACKX2(lo, hi, acc2[pp * T + t]);
            outb[(po + 8 * pp) * OSTR + 2 * q]     = fmaxf(lo + blo, 0.0f);
            outb[(po + 8 * pp) * OSTR + 2 * q + 1] = fmaxf(hi + bhi, 0.0f);
        }
    }
    // center rows (p = 32), 2 groups
    for (int idx = tid; idx < COUT * 2; idx += 256) {
        int o = idx & (COUT - 1);
        int grp = idx / COUT;
        const float* ir = in + grp * GROWS + 32 * GSTR;
        const float* wr = Wsh + (o >> 1) * 136 + (o & 1);
        float s = 0.0f;
#pragma unroll 8
        for (int c = 0; c < 64; c++) s += ir[c] * wr[c * 2];
        out[grp * OROWS + 32 * OSTR + o] = fmaxf(s + bsh[o], 0.0f);
    }
}

__device__ __forceinline__ void attn_reduce(float* e, int d, const float* gfb,
                                            int po, int team, float* outv) {
    const unsigned FULL = 0xffffffffu;
    float mx = -1e30f;
#pragma unroll
    for (int pp = 0; pp < 4; pp++) {
        float v = e[pp];
        v = (v >= 0.0f) ? v : (ALPHAc * v);
        e[pp] = v;
        mx = fmaxf(mx, v);
    }
    mx = fmaxf(mx, __shfl_xor_sync(FULL, mx, 1));
    mx = fmaxf(mx, __shfl_xor_sync(FULL, mx, 2));
    mx = fmaxf(mx, __shfl_xor_sync(FULL, mx, 4));
    float den = 0.0f;
#pragma unroll
    for (int pp = 0; pp < 4; pp++) { e[pp] = expf(e[pp] - mx); den += e[pp]; }
    den += __shfl_xor_sync(FULL, den, 1);
    den += __shfl_xor_sync(FULL, den, 2);
    den += __shfl_xor_sync(FULL, den, 4);
    float rd = 1.0f / den;
    float val = 0.0f;
#pragma unroll
    for (int pp = 0; pp < 4; pp++)
        val += e[pp] * rd * gfb[(po + 8 * pp) * GFSTR + d];
    val += __shfl_xor_sync(FULL, val, 1);
    val += __shfl_xor_sync(FULL, val, 2);
    val += __shfl_xor_sync(FULL, val, 4);
    if (po == 0) outv[d * 2 + team] = val;
}

__global__ void __launch_bounds__(256) mega_kernel(const float* __restrict__ xyz,
                                                   const int* __restrict__ tgt,
                                                   float* __restrict__ d_out) {
    extern __shared__ float sm[];
    __shared__ unsigned rvs[2][8];
    __shared__ int      ris[2][8];
    __shared__ int      s_item;

    int blk = blockIdx.x;
    int tid = threadIdx.x;
    int lane = tid & 31, wid = tid >> 5;
    const unsigned FULL = 0xffffffffu;

    if (blk < 8) {
        // ======================= FPS producer (256 thr x 32 pts) =======================
        float* xs = sm;
        float* ys = sm + Nn;
        float* zs = sm + 2 * Nn;
        int b = blk;
        float dd[32];
        u64 px2[16], py2[16], pz2[16];
#pragma unroll
        for (int m = 0; m < 16; m++) {
            int i0 = tid + (2 * m) * 256;
            int i1 = tid + (2 * m + 1) * 256;
            float x0 = xyz[((size_t)b * 3 + 0) * Nn + i0];
            float x1 = xyz[((size_t)b * 3 + 0) * Nn + i1];
            float y0 = xyz[((size_t)b * 3 + 1) * Nn + i0];
            float y1 = xyz[((size_t)b * 3 + 1) * Nn + i1];
            float z0 = xyz[((size_t)b * 3 + 2) * Nn + i0];
            float z1 = xyz[((size_t)b * 3 + 2) * Nn + i1];
            xs[i0] = x0; xs[i1] = x1;
            ys[i0] = y0; ys[i1] = y1;
            zs[i0] = z0; zs[i1] = z1;
            PACKX2(px2[m], x0, x1);
            PACKX2(py2[m], y0, y1);
            PACKX2(pz2[m], z0, z1);
            dd[2 * m] = 1e10f; dd[2 * m + 1] = 1e10f;
        }
        __syncthreads();

        int cur = 0;
        for (int s = 0; s < Ss; s++) {
            if (tid == 0) st_rel(&g_fps_idx[b * Ss + s], cur);
            float ncx = -xs[cur], ncy = -ys[cur], ncz = -zs[cur];
            u64 cx2, cy2, cz2;
            PACKX2(cx2, ncx, ncx);
            PACKX2(cy2, ncy, ncy);
            PACKX2(cz2, ncz, ncz);

#pragma unroll
            for (int m = 0; m < 16; m++) {
                u64 dx2, dy2, dz2, t2;
                ADDX2(dx2, px2[m], cx2);
                ADDX2(dy2, py2[m], cy2);
                ADDX2(dz2, pz2[m], cz2);
                MULX2(t2, dx2, dx2);
                FMAX2(t2, dy2, dy2, t2);
                FMAX2(t2, dz2, dz2, t2);
                float dl, dh;
                UNPACKX2(dl, dh, t2);
                dd[2 * m]     = fminf(dd[2 * m], dl);
                dd[2 * m + 1] = fminf(dd[2 * m + 1], dh);
            }
            // max tournament tree over dd[0..31]
            float tv[16];
#pragma unroll
            for (int j = 0; j < 16; j++) tv[j] = fmaxf(dd[2 * j], dd[2 * j + 1]);
#pragma unroll
            for (int j = 0; j < 8; j++) tv[j] = fmaxf(tv[j], tv[j + 8]);
#pragma unroll
            for (int j = 0; j < 4; j++) tv[j] = fmaxf(tv[j], tv[j + 4]);
            tv[0] = fmaxf(tv[0], tv[2]);
            tv[1] = fmaxf(tv[1], tv[3]);
            float best = fmaxf(tv[0], tv[1]);
            // min global index among equal maxima
            int ci[16];
#pragma unroll
            for (int j = 0; j < 16; j++) {
                int a0 = (dd[2 * j]     == best) ? (tid + ((2 * j) << 8))     : 0x7FFFFFFF;
                int a1 = (dd[2 * j + 1] == best) ? (tid + ((2 * j + 1) << 8)) : 0x7FFFFFFF;
                ci[j] = min(a0, a1);
            }
#pragma unroll
            for (int j = 0; j < 8; j++) ci[j] = min(ci[j], ci[j + 8]);
#pragma unroll
            for (int j = 0; j < 4; j++) ci[j] = min(ci[j], ci[j + 4]);
            ci[0] = min(ci[0], ci[2]);
            ci[1] = min(ci[1], ci[3]);
            int bi = min(ci[0], ci[1]);

            unsigned key = __float_as_uint(best);
            unsigned wkey = __reduce_max_sync(FULL, key);
            unsigned cand = (key == wkey) ? (unsigned)bi : 0xffffffffu;
            unsigned wbi = __reduce_min_sync(FULL, cand);

            int par = s & 1;
            if (lane == 0) { rvs[par][wid] = wkey; ris[par][wid] = (int)wbi; }
            __syncthreads();
            unsigned k2 = rvs[par][lane & 7];
            int      i2 = ris[par][lane & 7];
            unsigned m2 = __reduce_max_sync(FULL, k2);
            unsigned c2 = (k2 == m2) ? (unsigned)i2 : 0xffffffffu;
            cur = (int)__reduce_min_sync(FULL, c2);
        }
        return;
    }

    // ======================= persistent consumer (R7 shape) =======================
    float* bufA = sm;                    // 4488
    float* bufB = sm + 4488;             // 4488
    float* gf   = sm + 8976;             // 8712
    float* Wsh  = sm + 17688;            // 8704
    float* bsh  = sm + 26392;            // 128
    float* dpx  = sm + 26520;            // 64
    float* dpy  = sm + 26584;            // 64
    float* dpz  = sm + 26648;            // 64
    float* outv = sm + 26712;            // 256
    int*   ballsm = (int*)(sm + 26968);  // 64 ints
    float* nxyz = sm + 27032;            // 6 floats

    int w = wid;
    for (;;) {
        __syncthreads();
        if (tid == 0) s_item = atomicAdd(&g_ctr, 1);
        __syncthreads();
        int item = s_item;
        if (item >= (Bb * Ss) / 2) break;
        int bB = item & 7;
        int s0 = (item >> 3) * 2;
        int g0 = bB * Ss + s0;

        // ---- wait for our 2 centroids ----
        if (tid < 2) {
            while (ld_acq(&g_fps_idx[g0 + tid]) < 0) __nanosleep(64);
        }
        __syncthreads();

        // ---- ball query + center gathers: warps 0,1 (one group each) ----
        if (w < 2) {
            int g = g0 + w;
            int s = s0 + w;
            int ci = g_fps_idx[g];
            const float* xb = xyz + (size_t)bB * 3 * Nn;
            float cx = xb[ci], cy = xb[Nn + ci], cz = xb[2 * Nn + ci];
            if (lane == 0) {
                nxyz[w * 3 + 0] = cx;
                nxyz[w * 3 + 1] = cy;
                nxyz[w * 3 + 2] = cz;
                d_out[((size_t)bB * 3 + 0) * Ss + s] = cx;
                d_out[((size_t)bB * 3 + 1) * Ss + s] = cy;
                d_out[((size_t)bB * 3 + 2) * Ss + s] = cz;
                d_out[(size_t)Bb * 3 * Ss + (size_t)Bb * 128 * Ss + g] = (float)tgt[(size_t)bB * Nn + ci];
            }
            int cnt = 0, firstn = 0;
            for (int basen = 0; basen < Nn; basen += 32) {
                int n = basen + lane;
                float dx = xb[n] - cx, dy = xb[Nn + n] - cy, dz = xb[2 * Nn + n] - cz;
                float d = dx * dx + dy * dy + dz * dz;
                bool inb = (d <= 0.25f);
                unsigned m = __ballot_sync(FULL, inb);
                if (cnt == 0 && m) firstn = basen + __ffs(m) - 1;
                int pos = cnt + __popc(m & ((1u << lane) - 1u));
                if (inb && pos < Kk) ballsm[w * Kk + pos] = n;
                cnt += __popc(m);
                if (cnt >= Kk) break;
            }
            for (int j = cnt + lane; j < Kk; j += 32)
                ballsm[w * Kk + j] = firstn;
        }
        __syncthreads();

        // ---- load 2*33 feature rows ----
#pragma unroll
        for (int grp = 0; grp < 2; grp++) {
            for (int p = w; p < 33; p += 8) {
                int src = (p < 32) ? ballsm[grp * Kk + p] : g_fps_idx[g0 + grp];
                float2 v = ((const float2*)(g_F + (size_t)(bB * Nn + src) * 64))[lane];
                bufA[grp * GROWS + p * GSTR + lane * 2]     = v.x;
                bufA[grp * GROWS + p * GSTR + lane * 2 + 1] = v.y;
            }
        }
        __syncthreads();
        if (tid < 64) {
            int grp = tid >> 5, k = tid & 31;
            float nx = nxyz[grp * 3 + 0];
            float ny = nxyz[grp * 3 + 1];
            float nz = nxyz[grp * 3 + 2];
            float* row = bufA + grp * GROWS + k * GSTR;
            float gx = row[0], gy = row[1], gz = row[2];
            row[0] = gx - nx; row[1] = gy - ny; row[2] = gz - nz;   // grouped_norm
            dpx[grp * 32 + k] = nx - gx;                            // delta_p
            dpy[grp * 32 + k] = ny - gy;
            dpz[grp * 32 + k] = nz - gz;
        }

        // ---- 3-layer MLP (f32x2), verbatim R7 ----
        mlp_layer<64, GSTR, GROWS>(g_W0p, g_b0, Wsh, bsh, bufA, bufB, tid);
        mlp_layer<64, GSTR, GROWS>(g_W1p, g_b1, Wsh, bsh, bufB, bufA, tid);
        mlp_layer<128, GFSTR, GFROWS>(g_W2p, g_b2, Wsh, bsh, bufA, gf, tid);
        __syncthreads();

        // ---- build cat[2][32][132] ----
        float* cat = bufA;
        for (int idx = tid; idx < 2 * 32 * 131; idx += 256) {
            int grp = idx / (32 * 131);
            int r = idx - grp * (32 * 131);
            int k = r / 131;
            int c = r - k * 131;
            const float* gfb = gf + grp * GFROWS;
            float v;
            if (c == 0)      v = dpx[grp * 32 + k];
            else if (c == 1) v = dpy[grp * 32 + k];
            else if (c == 2) v = dpz[grp * 32 + k];
            else             v = gfb[32 * GFSTR + (c - 3)] - gfb[k * GFSTR + (c - 3)];
            cat[grp * CATROWS + k * GFSTR + c] = v;
        }
        if (tid < 64) cat[(tid >> 5) * CATROWS + (tid & 31) * GFSTR + 131] = 0.0f;

        // ---- e = cat @ a (f32x2, 4pt x 4 output-pairs) ----
        int team = tid >> 7, l = tid & 127, po = l & 7, og = l >> 3;
        const float* catb = cat + team * CATROWS;
        u64 acc2[16];
#pragma unroll
        for (int i = 0; i < 16; i++) acc2[i] = 0ull;

        for (int t = 0; t < 3; t++) {
            __syncthreads();
            if (t < 2) {
                const float4* src = (const float4*)(g_Ap + t * 8704);
                float4* dst = (float4*)Wsh;
                for (int idx = tid; idx < 2176; idx += 256) dst[idx] = src[idx];
            } else {
                for (int idx = tid; idx < 512; idx += 256) {
                    int qq = idx >> 3, ww = idx & 7;
                    Wsh[qq * 136 + ww] = g_Ap[2 * 8704 + qq * 136 + ww];
                }
            }
            __syncthreads();
            int c0 = t * 64;
            int nch = (t < 2) ? 16 : 1;
#pragma unroll 2
            for (int cc = 0; cc < nch; cc++) {
                u64 ivd[4][4];
#pragma unroll
                for (int pp = 0; pp < 4; pp++) {
                    float4 iv = *(const float4*)(catb + (po + 8 * pp) * GFSTR + c0 + cc * 4);
                    PACKX2(ivd[pp][0], iv.x, iv.x);
                    PACKX2(ivd[pp][1], iv.y, iv.y);
                    PACKX2(ivd[pp][2], iv.z, iv.z);
                    PACKX2(ivd[pp][3], iv.w, iv.w);
                }
#pragma unroll
                for (int tq = 0; tq < 4; tq++) {
                    int qq = og + 16 * tq;
                    ulonglong2 w01 = *(const ulonglong2*)(Wsh + qq * 136 + cc * 8);
                    ulonglong2 w23 = *(const ulonglong2*)(Wsh + qq * 136 + cc * 8 + 4);
#pragma unroll
                    for (int pp = 0; pp < 4; pp++) {
                        FMAX2(acc2[pp * 4 + tq], ivd[pp][0], w01.x, acc2[pp * 4 + tq]);
                        FMAX2(acc2[pp * 4 + tq], ivd[pp][1], w01.y, acc2[pp * 4 + tq]);
                        FMAX2(acc2[pp * 4 + tq], ivd[pp][2], w23.x, acc2[pp * 4 + tq]);
                        FMAX2(acc2[pp * 4 + tq], ivd[pp][3], w23.y, acc2[pp * 4 + tq]);
                    }
                }
            }
        }

        // ---- leaky relu + softmax + weighted sum ----
        const float* gfb = gf + team * GFROWS;
#pragma unroll
        for (int tq = 0; tq < 4; tq++) {
            int qq = og + 16 * tq;
            float elo[4], ehi[4];
#pragma unroll
            for (int pp = 0; pp < 4; pp++)
                UNPACKX2(elo[pp], ehi[pp], acc2[pp * 4 + tq]);
            attn_reduce(elo, 2 * qq,     gfb, po, team, outv);
            attn_reduce(ehi, 2 * qq + 1, gfb, po, team, outv);
        }
        __syncthreads();

        // ---- coalesced output: 2 consecutive s per d ----
        if (tid < 128) {
            float2 v = *(const float2*)(outv + tid * 2);
            *(float2*)(d_out + (size_t)Bb * 3 * Ss + (size_t)bB * 128 * Ss
                       + (size_t)tid * Ss + s0) = v;
        }
    }
}

// ---------------- launch ----------------
extern "C" void kernel_launch(void* const* d_in, const int* in_sizes, int n_in,
                              void* d_out, int out_size) {
    const float* xyz = (const float*)d_in[0];
    const float* pts = (const float*)d_in[1];
    const int*   tgt = (const int*)d_in[2];
    const float* w0 = (const float*)d_in[3];
    const float* b0 = (const float*)d_in[4];
    const float* g0 = (const float*)d_in[5];
    const float* be0 = (const float*)d_in[6];
    const float* m0 = (const float*)d_in[7];
    const float* v0 = (const float*)d_in[8];
    const float* w1 = (const float*)d_in[9];
    const float* b1 = (const float*)d_in[10];
    const float* g1 = (const float*)d_in[11];
    const float* be1 = (const float*)d_in[12];
    const float* m1 = (const float*)d_in[13];
    const float* v1 = (const float*)d_in[14];
    const float* w2 = (const float*)d_in[15];
    const float* b2 = (const float*)d_in[16];
    const float* g2 = (const float*)d_in[17];
    const float* be2 = (const float*)d_in[18];
    const float* m2 = (const float*)d_in[19];
    const float* v2 = (const float*)d_in[20];
    const float* a  = (const float*)d_in[21];
    float* out = (float*)d_out;

    cudaFuncSetAttribute(mega_kernel, cudaFuncAttributeMaxDynamicSharedMemorySize, SMFLOATS * 4);

    prep_kernel<<<1218, 256>>>(xyz, pts,
                               w0, b0, g0, be0, m0, v0,
                               w1, b1, g1, be1, m1, v1,
                               w2, b2, g2, be2, m2, v2, a);
    mega_kernel<<<296, 256, SMFLOATS * 4>>>(xyz, tgt, out);
}

// round 16
// speedup vs baseline: 1.9476x; 1.9476x over previous
#include <cuda_runtime.h>
#include <cuda_bf16.h>
#include <math.h>

#define Bb 8
#define Nn 8192
#define Ss 2048
#define Kk 32
#define EPSc 1e-5f
#define ALPHAc 0.2f

typedef unsigned long long u64;

// ---- packed f32x2 helpers (Blackwell) ----
#define PACKX2(out, lo, hi) \
    asm("mov.b64 %0, {%1, %2};" : "=l"(out) : "f"(lo), "f"(hi))
#define UNPACKX2(lo, hi, in) \
    asm("mov.b64 {%0, %1}, %2;" : "=f"(lo), "=f"(hi) : "l"(in))
#define ADDX2(d, a, b) \
    asm("add.rn.f32x2 %0, %1, %2;" : "=l"(d) : "l"(a), "l"(b))
#define MULX2(d, a, b) \
    asm("mul.rn.f32x2 %0, %1, %2;" : "=l"(d) : "l"(a), "l"(b))
#define FMAX2(d, a, b, c) \
    asm("fma.rn.f32x2 %0, %1, %2, %3;" : "=l"(d) : "l"(a), "l"(b), "l"(c))

// ---------------- scratch (device globals; no allocations) ----------------
__device__ int   g_fps_idx[Bb * Ss];
__device__ int   g_ball_idx[Bb * Ss * Kk];
__device__ float g_newxyz[Bb * Ss * 3];
__device__ __align__(16) float g_F[(size_t)Bb * Nn * 64];   // [xyz(3)|points(61)]
// interleaved weights: Wp[pair][c][2], row pad 136 floats; W0||W1 merged
__device__ __align__(16) float g_W01p[2 * 32 * 136];
__device__ __align__(16) float g_W2p[64 * 136];
__device__ __align__(16) float g_Ap[3 * 8704];               // a interleaved, 3 c-tiles
__device__ float g_b0[64], g_b1[64], g_b2[128];

// ============================================================================
// FPS: one block per batch, 512 threads x 16 points, REDUX reductions.
// (verbatim R7)
// ============================================================================
__global__ void __launch_bounds__(512) fps_kernel(const float* __restrict__ xyz) {
    extern __shared__ float4 pts4[];                 // 8192 float4 = 128 KB
    __shared__ unsigned rv[2][16];
    __shared__ int      ri[2][16];

    int b = blockIdx.x;
    int tid = threadIdx.x;
    int lane = tid & 31, wid = tid >> 5;             // 16 warps
    const unsigned FULL = 0xffffffffu;

    float xr[16], yr[16], zr[16], dd[16];
    u64 px2[8], py2[8], pz2[8];
#pragma unroll
    for (int j = 0; j < 16; j++) {
        int i = tid + j * 512;
        xr[j] = xyz[((size_t)b * 3 + 0) * Nn + i];
        yr[j] = xyz[((size_t)b * 3 + 1) * Nn + i];
        zr[j] = xyz[((size_t)b * 3 + 2) * Nn + i];
        pts4[i] = make_float4(xr[j], yr[j], zr[j], 0.0f);
        dd[j] = 1e10f;
    }
#pragma unroll
    for (int m = 0; m < 8; m++) {
        PACKX2(px2[m], xr[2 * m], xr[2 * m + 1]);
        PACKX2(py2[m], yr[2 * m], yr[2 * m + 1]);
        PACKX2(pz2[m], zr[2 * m], zr[2 * m + 1]);
    }
    __syncthreads();

    int cur = 0;
    for (int s = 0; s < Ss; s++) {
        if (tid == 0) g_fps_idx[b * Ss + s] = cur;
        float4 c = pts4[cur];
        float ncx = -c.x, ncy = -c.y, ncz = -c.z;
        u64 cx2, cy2, cz2;
        PACKX2(cx2, ncx, ncx);
        PACKX2(cy2, ncy, ncy);
        PACKX2(cz2, ncz, ncz);

        float best = -1.0f; int bi = 0;
#pragma unroll
        for (int m = 0; m < 8; m++) {
            u64 dx2, dy2, dz2, t2;
            ADDX2(dx2, px2[m], cx2);
            ADDX2(dy2, py2[m], cy2);
            ADDX2(dz2, pz2[m], cz2);
            MULX2(t2, dx2, dx2);
            FMAX2(t2, dy2, dy2, t2);
            FMAX2(t2, dz2, dz2, t2);
            float dl, dh;
            UNPACKX2(dl, dh, t2);
            float n0 = fminf(dd[2 * m], dl);     dd[2 * m] = n0;
            float n1 = fminf(dd[2 * m + 1], dh); dd[2 * m + 1] = n1;
            if (n0 > best) { best = n0; bi = tid + (2 * m) * 512; }       // ascending idx
            if (n1 > best) { best = n1; bi = tid + (2 * m + 1) * 512; }
        }
        // stage 1: warp argmax via REDUX (exact smallest-idx tie-break)
        unsigned key = __float_as_uint(best);
        unsigned wkey = __reduce_max_sync(FULL, key);
        unsigned cand = (key == wkey) ? (unsigned)bi : 0xffffffffu;
        unsigned wbi = __reduce_min_sync(FULL, cand);

        int par = s & 1;
        if (lane == 0) { rv[par][wid] = wkey; ri[par][wid] = (int)wbi; }
        __syncthreads();

        unsigned k2 = rv[par][lane & 15];
        int      i2 = ri[par][lane & 15];
        unsigned m2 = __reduce_max_sync(FULL, k2);
        unsigned c2 = (k2 == m2) ? (unsigned)i2 : 0xffffffffu;
        cur = (int)__reduce_min_sync(FULL, c2);
    }
}

// ---------------- prep A: buildF (transpose features) ----------------
__global__ void __launch_bounds__(256) buildF_kernel(const float* __restrict__ xyz,
                                                     const float* __restrict__ pts) {
    __shared__ float tile[64][65];
    int b = blockIdx.x >> 7;
    int n0 = (blockIdx.x & 127) * 64;
    int tid = threadIdx.x;
    int nl = tid & 63;
    int cl = tid >> 6;
    for (int c = cl; c < 64; c += 4) {
        int n = n0 + nl;
        float v = (c < 3) ? xyz[((size_t)b * 3 + c) * Nn + n]
                          : pts[((size_t)b * 61 + (c - 3)) * Nn + n];
        tile[c][nl] = v;
    }
    __syncthreads();
    int c = tid & 63;
    int nb = tid >> 6;
    for (int nn = nb; nn < 64; nn += 4)
        g_F[((size_t)(b * Nn + n0 + nn)) * 64 + c] = tile[c][nn];
}

// ---------------- prep B: fold BN -> interleaved pair weights ----------------
__global__ void __launch_bounds__(256) foldw_kernel(
    const float* w0, const float* b0, const float* g0, const float* be0, const float* m0, const float* v0,
    const float* w1, const float* b1, const float* g1, const float* be1, const float* m1, const float* v1,
    const float* w2, const float* b2, const float* g2, const float* be2, const float* m2, const float* v2) {
    int t = blockIdx.x * 256 + threadIdx.x;
    if (t < 4096) {
        int o = t >> 6, c = t & 63;
        float sc = g0[o] / sqrtf(v0[o] + EPSc);
        g_W01p[(o >> 1) * 136 + c * 2 + (o & 1)] = w0[t] * sc;
        if (c == 0) g_b0[o] = (b0[o] - m0[o]) * sc + be0[o];
    } else if (t < 8192) {
        int i = t - 4096;
        int o = i >> 6, c = i & 63;
        float sc = g1[o] / sqrtf(v1[o] + EPSc);
        g_W01p[4352 + (o >> 1) * 136 + c * 2 + (o & 1)] = w1[i] * sc;
        if (c == 0) g_b1[o] = (b1[o] - m1[o]) * sc + be1[o];
    } else if (t < 16384) {
        int i = t - 8192;
        int o = i >> 6, c = i & 63;
        float sc = g2[o] / sqrtf(v2[o] + EPSc);
        g_W2p[(o >> 1) * 136 + c * 2 + (o & 1)] = w2[i] * sc;
        if (c == 0) g_b2[o] = (b2[o] - m2[o]) * sc + be2[o];
    }
}

// ---------------- prep C: interleave attention matrix a ----------------
__global__ void __launch_bounds__(256) folda_kernel(const float* __restrict__ a) {
    int e = blockIdx.x * 256 + threadIdx.x;
    if (e < 131 * 128) {
        int c = e >> 7, d = e & 127;
        int tt = c >> 6, cc = c & 63;
        g_Ap[tt * 8704 + (d >> 1) * 136 + cc * 2 + (d & 1)] = a[(size_t)c * 128 + d];
    }
}

// ---------------- ball query + center gather: one warp per group ----------------
__global__ void __launch_bounds__(256) ball_gather_kernel(const float* __restrict__ xyz,
                                                          const int* __restrict__ tgt,
                                                          float* __restrict__ out) {
    int gw = blockIdx.x * 8 + (threadIdx.x >> 5);
    int lane = threadIdx.x & 31;
    int b = gw >> 11, s = gw & 2047;
    int ci = g_fps_idx[gw];
    const float* xb = xyz + (size_t)b * 3 * Nn;
    float cx = xb[ci];
    float cy = xb[Nn + ci];
    float cz = xb[2 * Nn + ci];
    if (lane == 0) {
        g_newxyz[gw * 3 + 0] = cx;
        g_newxyz[gw * 3 + 1] = cy;
        g_newxyz[gw * 3 + 2] = cz;
        out[((size_t)b * 3 + 0) * Ss + s] = cx;
        out[((size_t)b * 3 + 1) * Ss + s] = cy;
        out[((size_t)b * 3 + 2) * Ss + s] = cz;
        out[(size_t)Bb * 3 * Ss + (size_t)Bb * 128 * Ss + gw] = (float)tgt[(size_t)b * Nn + ci];
    }
    int cnt = 0, firstn = 0;
    for (int base = 0; base < Nn; base += 32) {
        int n = base + lane;
        float dx = xb[n] - cx, dy = xb[Nn + n] - cy, dz = xb[2 * Nn + n] - cz;
        float d = dx * dx + dy * dy + dz * dz;
        bool inb = (d <= 0.25f);
        unsigned m = __ballot_sync(0xffffffffu, inb);
        if (cnt == 0 && m) firstn = base + __ffs(m) - 1;
        int pos = cnt + __popc(m & ((1u << lane) - 1u));
        if (inb && pos < Kk) g_ball_idx[(size_t)gw * Kk + pos] = n;
        cnt += __popc(m);
        if (cnt >= Kk) break;
    }
    for (int j = cnt + lane; j < Kk; j += 32)
        g_ball_idx[(size_t)gw * Kk + j] = firstn;
}

// ============================================================================
// Fused MLP + attention (R7 shape: 2 groups/block, 256 threads, 107.9 KB smem,
// 2 CTAs/SM), with bit-exact phase reductions:
//  - L0+L1 share one Wsh fill (W0||W1 = 8704 fl exactly)
//  - e-GEMM t=2 tile stashed in bufB slack during cat build (no fill/barriers)
//  - center-row (p=32) dots packed as FMAX2 pairs (same accumulation order)
// ============================================================================
#define GSTR 68
#define GROWS 2244          // 33*68
#define GFSTR 132
#define GFROWS 4356         // 33*132
#define CATROWS 4224        // 32*132

// weights already resident at Wl/bl; computes one layer (2 groups)
template <int COUT, int OSTR, int OROWS>
__device__ __forceinline__ void mlp_compute(const float* Wl, const float* bl,
                                            const float* in, float* out, int tid) {
    constexpr int T = COUT / 32;                 // output-pairs per thread (main tile)
    int team = tid >> 7, l = tid & 127, po = l & 7, og = l >> 3;
    const float* inb = in + team * GROWS;
    float* outb = out + team * OROWS;

    u64 acc2[4 * T];
#pragma unroll
    for (int i = 0; i < 4 * T; i++) acc2[i] = 0ull;

#pragma unroll 2
    for (int cc = 0; cc < 16; cc++) {
        u64 ivd[4][4];
#pragma unroll
        for (int pp = 0; pp < 4; pp++) {
            float4 iv = *(const float4*)(inb + (po + 8 * pp) * GSTR + cc * 4);
            PACKX2(ivd[pp][0], iv.x, iv.x);
            PACKX2(ivd[pp][1], iv.y, iv.y);
            PACKX2(ivd[pp][2], iv.z, iv.z);
            PACKX2(ivd[pp][3], iv.w, iv.w);
        }
#pragma unroll
        for (int t = 0; t < T; t++) {
            int q = og + 16 * t;
            ulonglong2 w01 = *(const ulonglong2*)(Wl + q * 136 + cc * 8);
            ulonglong2 w23 = *(const ulonglong2*)(Wl + q * 136 + cc * 8 + 4);
#pragma unroll
            for (int pp = 0; pp < 4; pp++) {
                FMAX2(acc2[pp * T + t], ivd[pp][0], w01.x, acc2[pp * T + t]);
                FMAX2(acc2[pp * T + t], ivd[pp][1], w01.y, acc2[pp * T + t]);
                FMAX2(acc2[pp * T + t], ivd[pp][2], w23.x, acc2[pp * T + t]);
                FMAX2(acc2[pp * T + t], ivd[pp][3], w23.y, acc2[pp * T + t]);
            }
        }
    }
#pragma unroll
    for (int t = 0; t < T; t++) {
        int q = og + 16 * t;
        float blo = bl[2 * q], bhi = bl[2 * q + 1];
#pragma unroll
        for (int pp = 0; pp < 4; pp++) {
            float lo, hi;
            UNPACKX2(lo, hi, acc2[pp * T + t]);
            outb[(po + 8 * pp) * OSTR + 2 * q]     = fmaxf(lo + blo, 0.0f);
            outb[(po + 8 * pp) * OSTR + 2 * q + 1] = fmaxf(hi + bhi, 0.0f);
        }
    }
    // center row (p = 32), packed pairs: thread = one output-pair of one group
    constexpr int NP = COUT / 2;
    if (tid < NP * 2) {
        int grp = tid / NP, p = tid % NP;
        const float* ir = in + grp * GROWS + 32 * GSTR;
        u64 ca = 0ull;
#pragma unroll 4
        for (int cc = 0; cc < 16; cc++) {
            float4 iv = *(const float4*)(ir + cc * 4);
            u64 d0, d1, d2, d3;
            PACKX2(d0, iv.x, iv.x);
            PACKX2(d1, iv.y, iv.y);
            PACKX2(d2, iv.z, iv.z);
            PACKX2(d3, iv.w, iv.w);
            ulonglong2 w01 = *(const ulonglong2*)(Wl + p * 136 + cc * 8);
            ulonglong2 w23 = *(const ulonglong2*)(Wl + p * 136 + cc * 8 + 4);
            FMAX2(ca, d0, w01.x, ca);
            FMAX2(ca, d1, w01.y, ca);
            FMAX2(ca, d2, w23.x, ca);
            FMAX2(ca, d3, w23.y, ca);
        }
        float lo, hi;
        UNPACKX2(lo, hi, ca);
        out[grp * OROWS + 32 * OSTR + 2 * p]     = fmaxf(lo + bl[2 * p], 0.0f);
        out[grp * OROWS + 32 * OSTR + 2 * p + 1] = fmaxf(hi + bl[2 * p + 1], 0.0f);
    }
}

__device__ __forceinline__ void attn_reduce(float* e, int d, const float* gfb,
                                            int po, int team, float* outv) {
    const unsigned FULL = 0xffffffffu;
    float mx = -1e30f;
#pragma unroll
    for (int pp = 0; pp < 4; pp++) {
        float v = e[pp];
        v = (v >= 0.0f) ? v : (ALPHAc * v);
        e[pp] = v;
        mx = fmaxf(mx, v);
    }
    mx = fmaxf(mx, __shfl_xor_sync(FULL, mx, 1));
    mx = fmaxf(mx, __shfl_xor_sync(FULL, mx, 2));
    mx = fmaxf(mx, __shfl_xor_sync(FULL, mx, 4));
    float den = 0.0f;
#pragma unroll
    for (int pp = 0; pp < 4; pp++) { e[pp] = expf(e[pp] - mx); den += e[pp]; }
    den += __shfl_xor_sync(FULL, den, 1);
    den += __shfl_xor_sync(FULL, den, 2);
    den += __shfl_xor_sync(FULL, den, 4);
    float rd = 1.0f / den;
    float val = 0.0f;
#pragma unroll
    for (int pp = 0; pp < 4; pp++)
        val += e[pp] * rd * gfb[(po + 8 * pp) * GFSTR + d];
    val += __shfl_xor_sync(FULL, val, 1);
    val += __shfl_xor_sync(FULL, val, 2);
    val += __shfl_xor_sync(FULL, val, 4);
    if (po == 0) outv[d * 2 + team] = val;
}

__global__ void __launch_bounds__(256) fused_kernel(float* __restrict__ d_out) {
    extern __shared__ float sm[];
    float* bufA = sm;                  // 4488
    float* bufB = sm + 4488;           // 4488
    float* gf   = sm + 8976;           // 8712
    float* Wsh  = sm + 17688;          // 8704
    float* bsh  = sm + 26392;          // 128
    float* dpx  = sm + 26520;          // 64
    float* dpy  = sm + 26584;          // 64
    float* dpz  = sm + 26648;          // 64
    float* outv = sm + 26712;          // 256
    float* t2sh = sm + 8448;           // 512 fl in bufA+bufB slack (cat uses 8448)

    int tid = threadIdx.x;
    int w = tid >> 5, lane = tid & 31;
    int g0 = blockIdx.x * 2;
    int bB = g0 >> 11;

    // ---- load 2*33 feature rows ----
#pragma unroll
    for (int grp = 0; grp < 2; grp++) {
        int g = g0 + grp;
        for (int p = w; p < 33; p += 8) {
            int src = (p < 32) ? g_ball_idx[(size_t)g * Kk + p] : g_fps_idx[g];
            float2 v = ((const float2*)(g_F + (size_t)(bB * Nn + src) * 64))[lane];
            bufA[grp * GROWS + p * GSTR + lane * 2]     = v.x;
            bufA[grp * GROWS + p * GSTR + lane * 2 + 1] = v.y;
        }
    }
    __syncthreads();
    if (tid < 64) {
        int grp = tid >> 5, k = tid & 31;
        int g = g0 + grp;
        float nx = g_newxyz[g * 3 + 0];
        float ny = g_newxyz[g * 3 + 1];
        float nz = g_newxyz[g * 3 + 2];
        float* row = bufA + grp * GROWS + k * GSTR;
        float gx = row[0], gy = row[1], gz = row[2];
        row[0] = gx - nx; row[1] = gy - ny; row[2] = gz - nz;   // grouped_norm
        dpx[grp * 32 + k] = nx - gx;                            // delta_p
        dpy[grp * 32 + k] = ny - gy;
        dpz[grp * 32 + k] = nz - gz;
    }

    // ---- layers 0+1: single Wsh fill (W0||W1 = 8704 fl exactly) ----
    __syncthreads();
    {
        const float4* src = (const float4*)g_W01p;
        float4* dst = (float4*)Wsh;
        for (int idx = tid; idx < 2176; idx += 256) dst[idx] = src[idx];
    }
    if (tid < 64) bsh[tid] = g_b0[tid];
    else if (tid < 128) bsh[tid] = g_b1[tid - 64];
    __syncthreads();
    mlp_compute<64, GSTR, GROWS>(Wsh, bsh, bufA, bufB, tid);
    __syncthreads();
    mlp_compute<64, GSTR, GROWS>(Wsh + 4352, bsh + 64, bufB, bufA, tid);

    // ---- layer 2 ----
    __syncthreads();
    {
        const float4* src = (const float4*)g_W2p;
        float4* dst = (float4*)Wsh;
        for (int idx = tid; idx < 2176; idx += 256) dst[idx] = src[idx];
    }
    if (tid < 128) bsh[tid] = g_b2[tid];
    __syncthreads();
    mlp_compute<128, GFSTR, GFROWS>(Wsh, bsh, bufA, gf, tid);
    __syncthreads();

    // ---- build cat[2][32][132] + stash e-GEMM t=2 tile (same phase) ----
    float* cat = bufA;
    for (int idx = tid; idx < 2 * 32 * 131; idx += 256) {
        int grp = idx / (32 * 131);
        int r = idx - grp * (32 * 131);
        int k = r / 131;
        int c = r - k * 131;
        const float* gfb = gf + grp * GFROWS;
        float v;
        if (c == 0)      v = dpx[grp * 32 + k];
        else if (c == 1) v = dpy[grp * 32 + k];
        else if (c == 2) v = dpz[grp * 32 + k];
        else             v = gfb[32 * GFSTR + (c - 3)] - gfb[k * GFSTR + (c - 3)];
        cat[grp * CATROWS + k * GFSTR + c] = v;
    }
    if (tid < 64) cat[(tid >> 5) * CATROWS + (tid & 31) * GFSTR + 131] = 0.0f;
    for (int idx = tid; idx < 512; idx += 256)
        t2sh[idx] = g_Ap[2 * 8704 + (idx >> 3) * 136 + (idx & 7)];

    // ---- e = cat @ a  (131 -> 128): f32x2, 4pt x 4 output-pairs ----
    int team = tid >> 7, l = tid & 127, po = l & 7, og = l >> 3;
    const float* catb = cat + team * CATROWS;
    u64 acc2[16];
#pragma unroll
    for (int i = 0; i < 16; i++) acc2[i] = 0ull;

    for (int t = 0; t < 2; t++) {
        __syncthreads();     // protects Wsh overwrite; first one also covers cat+t2sh
        {
            const float4* src = (const float4*)(g_Ap + t * 8704);
            float4* dst = (float4*)Wsh;
            for (int idx = tid; idx < 2176; idx += 256) dst[idx] = src[idx];
        }
        __syncthreads();
        int c0 = t * 64;
#pragma unroll 2
        for (int cc = 0; cc < 16; cc++) {
            u64 ivd[4][4];
#pragma unroll
            for (int pp = 0; pp < 4; pp++) {
                float4 iv = *(const float4*)(catb + (po + 8 * pp) * GFSTR + c0 + cc * 4);
                PACKX2(ivd[pp][0], iv.x, iv.x);
                PACKX2(ivd[pp][1], iv.y, iv.y);
                PACKX2(ivd[pp][2], iv.z, iv.z);
                PACKX2(ivd[pp][3], iv.w, iv.w);
            }
#pragma unroll
            for (int tq = 0; tq < 4; tq++) {
                int q = og + 16 * tq;
                ulonglong2 w01 = *(const ulonglong2*)(Wsh + q * 136 + cc * 8);
                ulonglong2 w23 = *(const ulonglong2*)(Wsh + q * 136 + cc * 8 + 4);
#pragma unroll
                for (int pp = 0; pp < 4; pp++) {
                    FMAX2(acc2[pp * 4 + tq], ivd[pp][0], w01.x, acc2[pp * 4 + tq]);
                    FMAX2(acc2[pp * 4 + tq], ivd[pp][1], w01.y, acc2[pp * 4 + tq]);
                    FMAX2(acc2[pp * 4 + tq], ivd[pp][2], w23.x, acc2[pp * 4 + tq]);
                    FMAX2(acc2[pp * 4 + tq], ivd[pp][3], w23.y, acc2[pp * 4 + tq]);
                }
            }
        }
    }
    // t = 2 tile (c = 128..131) straight from t2sh; no fill, no barriers
    {
        u64 ivd[4][4];
#pragma unroll
        for (int pp = 0; pp < 4; pp++) {
            float4 iv = *(const float4*)(catb + (po + 8 * pp) * GFSTR + 128);
            PACKX2(ivd[pp][0], iv.x, iv.x);
            PACKX2(ivd[pp][1], iv.y, iv.y);
            PACKX2(ivd[pp][2], iv.z, iv.z);
            PACKX2(ivd[pp][3], iv.w, iv.w);
        }
#pragma unroll
        for (int tq = 0; tq < 4; tq++) {
            int q = og + 16 * tq;
            ulonglong2 w01 = *(const ulonglong2*)(t2sh + q * 8);
            ulonglong2 w23 = *(const ulonglong2*)(t2sh + q * 8 + 4);
#pragma unroll
            for (int pp = 0; pp < 4; pp++) {
                FMAX2(acc2[pp * 4 + tq], ivd[pp][0], w01.x, acc2[pp * 4 + tq]);
                FMAX2(acc2[pp * 4 + tq], ivd[pp][1], w01.y, acc2[pp * 4 + tq]);
                FMAX2(acc2[pp * 4 + tq], ivd[pp][2], w23.x, acc2[pp * 4 + tq]);
                FMAX2(acc2[pp * 4 + tq], ivd[pp][3], w23.y, acc2[pp * 4 + tq]);
            }
        }
    }

    // ---- leaky relu + softmax over k + weighted sum ----
    const float* gfb = gf + team * GFROWS;
#pragma unroll
    for (int tq = 0; tq < 4; tq++) {
        int q = og + 16 * tq;
        float elo[4], ehi[4];
#pragma unroll
        for (int pp = 0; pp < 4; pp++)
            UNPACKX2(elo[pp], ehi[pp], acc2[pp * 4 + tq]);
        attn_reduce(elo, 2 * q,     gfb, po, team, outv);
        attn_reduce(ehi, 2 * q + 1, gfb, po, team, outv);
    }
    __syncthreads();

    // ---- coalesced output: 2 consecutive s per d ----
    if (tid < 128) {
        float2 v = *(const float2*)(outv + tid * 2);
        int s0 = g0 & 2047;
        *(float2*)(d_out + (size_t)Bb * 3 * Ss + (size_t)bB * 128 * Ss
                   + (size_t)tid * Ss + s0) = v;
    }
}

// ---------------- launch ----------------
extern "C" void kernel_launch(void* const* d_in, const int* in_sizes, int n_in,
                              void* d_out, int out_size) {
    const float* xyz = (const float*)d_in[0];
    const float* pts = (const float*)d_in[1];
    const int*   tgt = (const int*)d_in[2];
    const float* w0 = (const float*)d_in[3];
    const float* b0 = (const float*)d_in[4];
    const float* g0 = (const float*)d_in[5];
    const float* be0 = (const float*)d_in[6];
    const float* m0 = (const float*)d_in[7];
    const float* v0 = (const float*)d_in[8];
    const float* w1 = (const float*)d_in[9];
    const float* b1 = (const float*)d_in[10];
    const float* g1 = (const float*)d_in[11];
    const float* be1 = (const float*)d_in[12];
    const float* m1 = (const float*)d_in[13];
    const float* v1 = (const float*)d_in[14];
    const float* w2 = (const float*)d_in[15];
    const float* b2 = (const float*)d_in[16];
    const float* g2 = (const float*)d_in[17];
    const float* be2 = (const float*)d_in[18];
    const float* m2 = (const float*)d_in[19];
    const float* v2 = (const float*)d_in[20];
    const float* a  = (const float*)d_in[21];
    float* out = (float*)d_out;

    cudaFuncSetAttribute(fps_kernel, cudaFuncAttributeMaxDynamicSharedMemorySize, Nn * 16);
    cudaFuncSetAttribute(fused_kernel, cudaFuncAttributeMaxDynamicSharedMemorySize, 26968 * 4);

    buildF_kernel<<<1024, 256>>>(xyz, pts);
    foldw_kernel<<<64, 256>>>(w0, b0, g0, be0, m0, v0,
                              w1, b1, g1, be1, m1, v1,
                              w2, b2, g2, be2, m2, v2);
    folda_kernel<<<66, 256>>>(a);
    fps_kernel<<<Bb, 512, Nn * 16>>>(xyz);
    ball_gather_kernel<<<(Bb * Ss) / 8, 256>>>(xyz, tgt, out);
    fused_kernel<<<Bb * Ss / 2, 256, 26968 * 4>>>(out);
}